// round 2
// baseline (speedup 1.0000x reference)
#include <cuda_runtime.h>

#define N_NODES 50000
#define N_EDGES 800000
#define D_IN    128
#define D_HID   128
#define D_MLP   256
#define D_OUT   10

// ---------------- scratch (static device globals: no allocations) ----------
__device__ float g_dis[N_NODES];            // deg -> deg^{-1/2}
__device__ float g_t [N_NODES * D_HID];     // t = h @ W (pre-aggregation)
__device__ float g_h [N_NODES * D_HID];     // aggregated hidden
__device__ float g_h2[N_NODES * D_MLP];     // MLP hidden

// ---------------- degree / norm ----------------
__global__ void k_init_deg(float* __restrict__ deg) {
    int i = blockIdx.x * blockDim.x + threadIdx.x;
    if (i < N_NODES) deg[i] = 1.0f;                     // self-loop
}

__global__ void k_count_deg(const int* __restrict__ ei, float* __restrict__ deg) {
    int e = blockIdx.x * blockDim.x + threadIdx.x;
    if (e < N_EDGES) {
        int d = ei[N_EDGES + e];                        // dst row
        atomicAdd(&deg[d], 1.0f);
    }
}

__global__ void k_rsqrt(float* __restrict__ d) {
    int i = blockIdx.x * blockDim.x + threadIdx.x;
    if (i < N_NODES) d[i] = rsqrtf(d[i]);
}

// ---------------- tiled SGEMM: C[M,Ncols] = op(A[M,K]) @ B[K,Ncols] (+bias)(+relu)
// block tile 128x128, BK=8, 256 threads, 8x8 microtile per thread
template<bool RELU_A, bool BIAS, bool RELU_OUT>
__global__ void __launch_bounds__(256) k_gemm(
    const float* __restrict__ A, const float* __restrict__ B,
    const float* __restrict__ bias, float* __restrict__ C,
    int M, int Ncols, int K)
{
    __shared__ float As[8][132];
    __shared__ float Bs[8][132];

    const int tid  = threadIdx.x;
    const int row0 = blockIdx.x * 128;
    const int col0 = blockIdx.y * 128;
    const int tx = tid & 15, ty = tid >> 4;

    // load mapping
    const int ar = tid >> 1,  ak = (tid & 1) * 4;   // A: 128 rows x 8 k
    const int bk = tid >> 5,  bc = (tid & 31) * 4;  // B: 8 k x 128 cols
    const bool arow_ok = (row0 + ar) < M;
    const float* Arow = A + (size_t)(row0 + ar) * K;
    const float* Bp   = B + (size_t)bk * Ncols + col0 + bc;

    float acc[8][8];
#pragma unroll
    for (int i = 0; i < 8; i++)
#pragma unroll
        for (int j = 0; j < 8; j++) acc[i][j] = 0.0f;

    for (int k0 = 0; k0 < K; k0 += 8) {
        float4 av = make_float4(0.f, 0.f, 0.f, 0.f);
        if (arow_ok) av = *(const float4*)(Arow + k0 + ak);
        if (RELU_A) {
            av.x = fmaxf(av.x, 0.f); av.y = fmaxf(av.y, 0.f);
            av.z = fmaxf(av.z, 0.f); av.w = fmaxf(av.w, 0.f);
        }
        As[ak + 0][ar] = av.x; As[ak + 1][ar] = av.y;
        As[ak + 2][ar] = av.z; As[ak + 3][ar] = av.w;

        float4 bv = *(const float4*)(Bp + (size_t)k0 * Ncols);
        *(float4*)&Bs[bk][bc] = bv;

        __syncthreads();
#pragma unroll
        for (int kk = 0; kk < 8; kk++) {
            float a[8], b[8];
            *(float4*)&a[0] = *(const float4*)&As[kk][ty * 8];
            *(float4*)&a[4] = *(const float4*)&As[kk][ty * 8 + 4];
            *(float4*)&b[0] = *(const float4*)&Bs[kk][tx * 8];
            *(float4*)&b[4] = *(const float4*)&Bs[kk][tx * 8 + 4];
#pragma unroll
            for (int i = 0; i < 8; i++)
#pragma unroll
                for (int j = 0; j < 8; j++)
                    acc[i][j] = fmaf(a[i], b[j], acc[i][j]);
        }
        __syncthreads();
    }

#pragma unroll
    for (int i = 0; i < 8; i++) {
        int r = row0 + ty * 8 + i;
        if (r < M) {
            float* Crow = C + (size_t)r * Ncols + col0 + tx * 8;
#pragma unroll
            for (int jj = 0; jj < 8; jj += 4) {
                float4 o;
                o.x = acc[i][jj + 0]; o.y = acc[i][jj + 1];
                o.z = acc[i][jj + 2]; o.w = acc[i][jj + 3];
                if (BIAS) {
                    const float* bp = bias + col0 + tx * 8 + jj;
                    o.x += bp[0]; o.y += bp[1]; o.z += bp[2]; o.w += bp[3];
                }
                if (RELU_OUT) {
                    o.x = fmaxf(o.x, 0.f); o.y = fmaxf(o.y, 0.f);
                    o.z = fmaxf(o.z, 0.f); o.w = fmaxf(o.w, 0.f);
                }
                *(float4*)(Crow + jj) = o;
            }
        }
    }
}

// ---------------- h[i] = dis[i]^2 * t[i] + bias   (self-loop + bias init) ----
__global__ void k_self_bias(const float* __restrict__ t, const float* __restrict__ dis,
                            const float* __restrict__ bias, float* __restrict__ h)
{
    int idx = blockIdx.x * blockDim.x + threadIdx.x;   // over N_NODES*32 float4s
    if (idx >= N_NODES * 32) return;
    int i  = idx >> 5;
    int j4 = idx & 31;
    float s = dis[i]; s = s * s;
    float4 v = ((const float4*)t)[idx];
    float4 b = ((const float4*)bias)[j4];
    float4 o;
    o.x = fmaf(s, v.x, b.x); o.y = fmaf(s, v.y, b.y);
    o.z = fmaf(s, v.z, b.z); o.w = fmaf(s, v.w, b.w);
    ((float4*)h)[idx] = o;
}

// ---------------- edge scatter: h[dst] += dis[src]*dis[dst] * t[src] --------
// one warp per edge, float4 per lane (32*4 = 128 features)
__global__ void __launch_bounds__(256) k_scatter(
    const int* __restrict__ ei, const float* __restrict__ dis,
    const float* __restrict__ t, float* __restrict__ h)
{
    int w    = (blockIdx.x * 256 + threadIdx.x) >> 5;
    int lane = threadIdx.x & 31;
    if (w >= N_EDGES) return;
    int s = __ldg(ei + w);
    int d = __ldg(ei + N_EDGES + w);
    float nrm = dis[s] * dis[d];
    float4 v = *(const float4*)(t + (size_t)s * D_HID + lane * 4);
    float* hd = h + (size_t)d * D_HID + lane * 4;
    atomicAdd(hd + 0, nrm * v.x);
    atomicAdd(hd + 1, nrm * v.y);
    atomicAdd(hd + 2, nrm * v.z);
    atomicAdd(hd + 3, nrm * v.w);
}

// ---------------- final: out[M,10] = H[M,256] @ W[256,10] + b ---------------
// one warp per row, W staged in shared
__global__ void __launch_bounds__(256) k_final(
    const float* __restrict__ H, const float* __restrict__ W,
    const float* __restrict__ b, float* __restrict__ out, int M)
{
    __shared__ float sW[D_MLP * D_OUT];
    __shared__ float sb[D_OUT];
    for (int k = threadIdx.x; k < D_MLP * D_OUT; k += 256) sW[k] = W[k];
    if (threadIdx.x < D_OUT) sb[threadIdx.x] = b[threadIdx.x];
    __syncthreads();

    int w    = (blockIdx.x * 256 + threadIdx.x) >> 5;
    int lane = threadIdx.x & 31;
    if (w >= M) return;

    const float* hrow = H + (size_t)w * D_MLP;
    float acc[D_OUT];
#pragma unroll
    for (int j = 0; j < D_OUT; j++) acc[j] = 0.0f;

#pragma unroll
    for (int kk = 0; kk < D_MLP / 32; kk++) {
        int k = kk * 32 + lane;
        float hv = hrow[k];
        const float* wr = &sW[k * D_OUT];
#pragma unroll
        for (int j = 0; j < D_OUT; j++) acc[j] = fmaf(hv, wr[j], acc[j]);
    }
#pragma unroll
    for (int j = 0; j < D_OUT; j++) {
#pragma unroll
        for (int off = 16; off; off >>= 1)
            acc[j] += __shfl_down_sync(0xffffffffu, acc[j], off);
    }
    if (lane == 0) {
#pragma unroll
        for (int j = 0; j < D_OUT; j++)
            out[(size_t)w * D_OUT + j] = acc[j] + sb[j];
    }
}

// ---------------------------------------------------------------------------
extern "C" void kernel_launch(void* const* d_in, const int* in_sizes, int n_in,
                              void* d_out, int out_size)
{
    const float* x   = (const float*)d_in[0];
    const int*   ei  = (const int*)d_in[1];     // int32: JAX default (x64 disabled)
    const float* W0  = (const float*)d_in[2];
    const float* b0  = (const float*)d_in[3];
    const float* W1  = (const float*)d_in[4];
    const float* b1  = (const float*)d_in[5];
    const float* Wm1 = (const float*)d_in[6];
    const float* bm1 = (const float*)d_in[7];
    const float* Wm2 = (const float*)d_in[8];
    const float* bm2 = (const float*)d_in[9];
    float* out = (float*)d_out;

    float *dis, *t, *h, *h2;
    cudaGetSymbolAddress((void**)&dis, g_dis);
    cudaGetSymbolAddress((void**)&t,   g_t);
    cudaGetSymbolAddress((void**)&h,   g_h);
    cudaGetSymbolAddress((void**)&h2,  g_h2);

    // degree -> deg^{-1/2}
    k_init_deg <<<(N_NODES + 255) / 256, 256>>>(dis);
    k_count_deg<<<(N_EDGES + 255) / 256, 256>>>(ei, dis);
    k_rsqrt    <<<(N_NODES + 255) / 256, 256>>>(dis);

    const dim3 gemm_grid1((N_NODES + 127) / 128, 1);
    const dim3 gemm_grid2((N_NODES + 127) / 128, 2);
    const int  sb_grid   = (N_NODES * 32 + 255) / 256;
    const int  sc_grid   = (N_EDGES * 32 + 255) / 256;

    // layer 0: t = x @ W0 ; h = agg(t) + b0  (relu deferred into next GEMM load)
    k_gemm<false, false, false><<<gemm_grid1, 256>>>(x, W0, nullptr, t, N_NODES, D_HID, D_IN);
    k_self_bias<<<sb_grid, 256>>>(t, dis, b0, h);
    k_scatter  <<<sc_grid, 256>>>(ei, dis, t, h);

    // layer 1: t = relu(h) @ W1 ; h = agg(t) + b1
    k_gemm<true, false, false><<<gemm_grid1, 256>>>(h, W1, nullptr, t, N_NODES, D_HID, D_HID);
    k_self_bias<<<sb_grid, 256>>>(t, dis, b1, h);
    k_scatter  <<<sc_grid, 256>>>(ei, dis, t, h);

    // MLP head
    k_gemm<false, true, true><<<gemm_grid2, 256>>>(h, Wm1, bm1, h2, N_NODES, D_MLP, D_HID);
    k_final<<<(N_NODES * 32 + 255) / 256, 256>>>(h2, Wm2, bm2, out, N_NODES);
}

// round 3
// speedup vs baseline: 1.6926x; 1.6926x over previous
#include <cuda_runtime.h>

#define N_NODES 50000
#define N_EDGES 800000
#define D_IN    128
#define D_HID   128
#define D_MLP   256
#define D_OUT   10

// ---------------- scratch (static device globals: no allocations) ----------
__device__ float g_dis[N_NODES];             // deg^{-1/2}
__device__ int   g_cnt[N_NODES];             // in-degree counts (no self-loop)
__device__ int   g_cur[N_NODES];             // fill cursors
__device__ int   g_rowoff[N_NODES + 1];      // CSR row offsets (by dst)
__device__ int   g_csrc[N_EDGES];            // CSR src indices
__device__ float g_t [N_NODES * D_HID];      // t = h @ W (pre-aggregation)
__device__ float g_h [N_NODES * D_HID];      // aggregated hidden
__device__ float g_h2[N_NODES * D_MLP];      // MLP hidden

// ---------------- CSR build ----------------
__global__ void k_zero(int* __restrict__ cnt, int* __restrict__ cur) {
    int i = blockIdx.x * blockDim.x + threadIdx.x;
    if (i < N_NODES) { cnt[i] = 0; cur[i] = 0; }
}

__global__ void k_count(const int* __restrict__ ei, int* __restrict__ cnt) {
    int e = blockIdx.x * blockDim.x + threadIdx.x;
    if (e < N_EDGES) atomicAdd(&cnt[ei[N_EDGES + e]], 1);
}

// single-block scan: rowoff = exclusive_scan(cnt); dis = rsqrt(cnt+1)
__global__ void __launch_bounds__(1024) k_scan(
    const int* __restrict__ cnt, int* __restrict__ rowoff, float* __restrict__ dis)
{
    __shared__ int part[1024];
    const int PER = (N_NODES + 1023) / 1024;    // 49
    int t = threadIdx.x;
    int base = t * PER;

    int sum = 0;
    for (int i = 0; i < PER; i++) {
        int idx = base + i;
        if (idx < N_NODES) sum += cnt[idx];
    }
    part[t] = sum;
    __syncthreads();
    // inclusive Hillis-Steele scan
    for (int off = 1; off < 1024; off <<= 1) {
        int v = (t >= off) ? part[t - off] : 0;
        __syncthreads();
        part[t] += v;
        __syncthreads();
    }
    int running = (t == 0) ? 0 : part[t - 1];
    for (int i = 0; i < PER; i++) {
        int idx = base + i;
        if (idx < N_NODES) {
            int c = cnt[idx];
            rowoff[idx] = running;
            running += c;
            dis[idx] = rsqrtf((float)(c + 1));
        }
    }
    if (t == 1023) rowoff[N_NODES] = part[1023];
}

__global__ void k_fill(const int* __restrict__ ei, const int* __restrict__ rowoff,
                       int* __restrict__ cur, int* __restrict__ csrc)
{
    int e = blockIdx.x * blockDim.x + threadIdx.x;
    if (e < N_EDGES) {
        int s = ei[e];
        int d = ei[N_EDGES + e];
        int pos = rowoff[d] + atomicAdd(&cur[d], 1);
        csrc[pos] = s;
    }
}

// ---------------- tiled SGEMM: C[M,Ncols] = op(A[M,K]) @ B[K,Ncols] (+bias)(+relu)
template<bool RELU_A, bool BIAS, bool RELU_OUT>
__global__ void __launch_bounds__(256) k_gemm(
    const float* __restrict__ A, const float* __restrict__ B,
    const float* __restrict__ bias, float* __restrict__ C,
    int M, int Ncols, int K)
{
    __shared__ float As[8][132];
    __shared__ float Bs[8][132];

    const int tid  = threadIdx.x;
    const int row0 = blockIdx.x * 128;
    const int col0 = blockIdx.y * 128;
    const int tx = tid & 15, ty = tid >> 4;

    const int ar = tid >> 1,  ak = (tid & 1) * 4;
    const int bk = tid >> 5,  bc = (tid & 31) * 4;
    const bool arow_ok = (row0 + ar) < M;
    const float* Arow = A + (size_t)(row0 + ar) * K;
    const float* Bp   = B + (size_t)bk * Ncols + col0 + bc;

    float acc[8][8];
#pragma unroll
    for (int i = 0; i < 8; i++)
#pragma unroll
        for (int j = 0; j < 8; j++) acc[i][j] = 0.0f;

    for (int k0 = 0; k0 < K; k0 += 8) {
        float4 av = make_float4(0.f, 0.f, 0.f, 0.f);
        if (arow_ok) av = *(const float4*)(Arow + k0 + ak);
        if (RELU_A) {
            av.x = fmaxf(av.x, 0.f); av.y = fmaxf(av.y, 0.f);
            av.z = fmaxf(av.z, 0.f); av.w = fmaxf(av.w, 0.f);
        }
        As[ak + 0][ar] = av.x; As[ak + 1][ar] = av.y;
        As[ak + 2][ar] = av.z; As[ak + 3][ar] = av.w;

        float4 bv = *(const float4*)(Bp + (size_t)k0 * Ncols);
        *(float4*)&Bs[bk][bc] = bv;

        __syncthreads();
#pragma unroll
        for (int kk = 0; kk < 8; kk++) {
            float a[8], b[8];
            *(float4*)&a[0] = *(const float4*)&As[kk][ty * 8];
            *(float4*)&a[4] = *(const float4*)&As[kk][ty * 8 + 4];
            *(float4*)&b[0] = *(const float4*)&Bs[kk][tx * 8];
            *(float4*)&b[4] = *(const float4*)&Bs[kk][tx * 8 + 4];
#pragma unroll
            for (int i = 0; i < 8; i++)
#pragma unroll
                for (int j = 0; j < 8; j++)
                    acc[i][j] = fmaf(a[i], b[j], acc[i][j]);
        }
        __syncthreads();
    }

#pragma unroll
    for (int i = 0; i < 8; i++) {
        int r = row0 + ty * 8 + i;
        if (r < M) {
            float* Crow = C + (size_t)r * Ncols + col0 + tx * 8;
#pragma unroll
            for (int jj = 0; jj < 8; jj += 4) {
                float4 o;
                o.x = acc[i][jj + 0]; o.y = acc[i][jj + 1];
                o.z = acc[i][jj + 2]; o.w = acc[i][jj + 3];
                if (BIAS) {
                    const float* bp = bias + col0 + tx * 8 + jj;
                    o.x += bp[0]; o.y += bp[1]; o.z += bp[2]; o.w += bp[3];
                }
                if (RELU_OUT) {
                    o.x = fmaxf(o.x, 0.f); o.y = fmaxf(o.y, 0.f);
                    o.z = fmaxf(o.z, 0.f); o.w = fmaxf(o.w, 0.f);
                }
                *(float4*)(Crow + jj) = o;
            }
        }
    }
}

// ---------------- CSR gather aggregation (one warp per dst node) ------------
// h[d] = dis[d] * sum_{e in row d} dis[src]*t[src] + dis[d]^2 * t[d] + bias
__global__ void __launch_bounds__(256) k_gather(
    const int* __restrict__ csrc, const int* __restrict__ rowoff,
    const float* __restrict__ dis, const float* __restrict__ t,
    const float* __restrict__ bias, float* __restrict__ h)
{
    int w    = (blockIdx.x * 256 + threadIdx.x) >> 5;
    int lane = threadIdx.x & 31;
    if (w >= N_NODES) return;

    int beg = rowoff[w], end = rowoff[w + 1];
    float dd = dis[w];

    float4 acc = make_float4(0.f, 0.f, 0.f, 0.f);
    for (int eb = beg; eb < end; eb += 32) {
        int n = end - eb; if (n > 32) n = 32;
        int   s_l  = (lane < n) ? __ldg(csrc + eb + lane) : 0;
        float ns_l = (lane < n) ? __ldg(dis + s_l) : 0.f;
#pragma unroll 4
        for (int j = 0; j < n; j++) {
            int   s  = __shfl_sync(0xffffffffu, s_l,  j);
            float ns = __shfl_sync(0xffffffffu, ns_l, j);
            float4 v = *(const float4*)(t + (size_t)s * D_HID + lane * 4);
            acc.x = fmaf(ns, v.x, acc.x); acc.y = fmaf(ns, v.y, acc.y);
            acc.z = fmaf(ns, v.z, acc.z); acc.w = fmaf(ns, v.w, acc.w);
        }
    }

    float4 tv = *(const float4*)(t + (size_t)w * D_HID + lane * 4);
    float4 bv = ((const float4*)bias)[lane];
    float dd2 = dd * dd;
    float4 o;
    o.x = fmaf(dd, acc.x, fmaf(dd2, tv.x, bv.x));
    o.y = fmaf(dd, acc.y, fmaf(dd2, tv.y, bv.y));
    o.z = fmaf(dd, acc.z, fmaf(dd2, tv.z, bv.z));
    o.w = fmaf(dd, acc.w, fmaf(dd2, tv.w, bv.w));
    *(float4*)(h + (size_t)w * D_HID + lane * 4) = o;
}

// ---------------- final: out[M,10] = H[M,256] @ W[256,10] + b ---------------
__global__ void __launch_bounds__(256) k_final(
    const float* __restrict__ H, const float* __restrict__ W,
    const float* __restrict__ b, float* __restrict__ out, int M)
{
    __shared__ float sW[D_MLP * D_OUT];
    __shared__ float sb[D_OUT];
    for (int k = threadIdx.x; k < D_MLP * D_OUT; k += 256) sW[k] = W[k];
    if (threadIdx.x < D_OUT) sb[threadIdx.x] = b[threadIdx.x];
    __syncthreads();

    int w    = (blockIdx.x * 256 + threadIdx.x) >> 5;
    int lane = threadIdx.x & 31;
    if (w >= M) return;

    const float* hrow = H + (size_t)w * D_MLP;
    float acc[D_OUT];
#pragma unroll
    for (int j = 0; j < D_OUT; j++) acc[j] = 0.0f;

#pragma unroll
    for (int kk = 0; kk < D_MLP / 32; kk++) {
        int k = kk * 32 + lane;
        float hv = hrow[k];
        const float* wr = &sW[k * D_OUT];
#pragma unroll
        for (int j = 0; j < D_OUT; j++) acc[j] = fmaf(hv, wr[j], acc[j]);
    }
#pragma unroll
    for (int j = 0; j < D_OUT; j++) {
#pragma unroll
        for (int off = 16; off; off >>= 1)
            acc[j] += __shfl_down_sync(0xffffffffu, acc[j], off);
    }
    if (lane == 0) {
#pragma unroll
        for (int j = 0; j < D_OUT; j++)
            out[(size_t)w * D_OUT + j] = acc[j] + sb[j];
    }
}

// ---------------------------------------------------------------------------
extern "C" void kernel_launch(void* const* d_in, const int* in_sizes, int n_in,
                              void* d_out, int out_size)
{
    const float* x   = (const float*)d_in[0];
    const int*   ei  = (const int*)d_in[1];     // int32 (JAX x64 disabled)
    const float* W0  = (const float*)d_in[2];
    const float* b0  = (const float*)d_in[3];
    const float* W1  = (const float*)d_in[4];
    const float* b1  = (const float*)d_in[5];
    const float* Wm1 = (const float*)d_in[6];
    const float* bm1 = (const float*)d_in[7];
    const float* Wm2 = (const float*)d_in[8];
    const float* bm2 = (const float*)d_in[9];
    float* out = (float*)d_out;

    float *dis, *t, *h, *h2;
    int *cnt, *cur, *rowoff, *csrc;
    cudaGetSymbolAddress((void**)&dis, g_dis);
    cudaGetSymbolAddress((void**)&t,   g_t);
    cudaGetSymbolAddress((void**)&h,   g_h);
    cudaGetSymbolAddress((void**)&h2,  g_h2);
    cudaGetSymbolAddress((void**)&cnt, g_cnt);
    cudaGetSymbolAddress((void**)&cur, g_cur);
    cudaGetSymbolAddress((void**)&rowoff, g_rowoff);
    cudaGetSymbolAddress((void**)&csrc, g_csrc);

    const int ngrid = (N_NODES + 255) / 256;
    const int egrid = (N_EDGES + 255) / 256;

    // ---- CSR build (by dst) + norms ----
    k_zero <<<ngrid, 256>>>(cnt, cur);
    k_count<<<egrid, 256>>>(ei, cnt);
    k_scan <<<1, 1024>>>(cnt, rowoff, dis);
    k_fill <<<egrid, 256>>>(ei, rowoff, cur, csrc);

    const dim3 gemm_grid1((N_NODES + 127) / 128, 1);
    const dim3 gemm_grid2((N_NODES + 127) / 128, 2);
    const int  gather_grid = (N_NODES * 32 + 255) / 256;

    // layer 0
    k_gemm<false, false, false><<<gemm_grid1, 256>>>(x, W0, nullptr, t, N_NODES, D_HID, D_IN);
    k_gather<<<gather_grid, 256>>>(csrc, rowoff, dis, t, b0, h);

    // layer 1 (relu fused into GEMM A-load)
    k_gemm<true, false, false><<<gemm_grid1, 256>>>(h, W1, nullptr, t, N_NODES, D_HID, D_HID);
    k_gather<<<gather_grid, 256>>>(csrc, rowoff, dis, t, b1, h);

    // MLP head
    k_gemm<false, true, true><<<gemm_grid2, 256>>>(h, Wm1, bm1, h2, N_NODES, D_MLP, D_HID);
    k_final<<<(N_NODES * 32 + 255) / 256, 256>>>(h2, Wm2, bm2, out, N_NODES);
}

// round 4
// speedup vs baseline: 2.4659x; 1.4568x over previous
#include <cuda_runtime.h>
#include <cstdint>

#define N_NODES 50000
#define N_EDGES 800000
#define D_IN    128
#define D_HID   128
#define D_MLP   256
#define D_OUT   10

// ---------------- scratch (static device globals: no allocations) ----------
__device__ float g_dis[N_NODES];             // deg^{-1/2}
__device__ int   g_cnt[N_NODES];             // in-degree counts (no self-loop)
__device__ int   g_cur[N_NODES];             // fill cursors
__device__ int   g_rowoff[N_NODES + 1];      // CSR row offsets (by dst)
__device__ int   g_csrc[N_EDGES];            // CSR src indices
__device__ float g_t [N_NODES * D_HID];      // t = h @ W (pre-aggregation)
__device__ float g_h [N_NODES * D_HID];      // aggregated hidden
__device__ float g_h2[N_NODES * D_MLP];      // MLP hidden

// ---------------- CSR build ----------------
__global__ void k_zero(int* __restrict__ cnt, int* __restrict__ cur) {
    int i = blockIdx.x * blockDim.x + threadIdx.x;
    if (i < N_NODES) { cnt[i] = 0; cur[i] = 0; }
}

__global__ void k_count(const int* __restrict__ ei, int* __restrict__ cnt) {
    int e = blockIdx.x * blockDim.x + threadIdx.x;
    if (e < N_EDGES) atomicAdd(&cnt[ei[N_EDGES + e]], 1);
}

__global__ void __launch_bounds__(1024) k_scan(
    const int* __restrict__ cnt, int* __restrict__ rowoff, float* __restrict__ dis)
{
    __shared__ int part[1024];
    const int PER = (N_NODES + 1023) / 1024;    // 49
    int t = threadIdx.x;
    int base = t * PER;

    int sum = 0;
    for (int i = 0; i < PER; i++) {
        int idx = base + i;
        if (idx < N_NODES) sum += cnt[idx];
    }
    part[t] = sum;
    __syncthreads();
    for (int off = 1; off < 1024; off <<= 1) {
        int v = (t >= off) ? part[t - off] : 0;
        __syncthreads();
        part[t] += v;
        __syncthreads();
    }
    int running = (t == 0) ? 0 : part[t - 1];
    for (int i = 0; i < PER; i++) {
        int idx = base + i;
        if (idx < N_NODES) {
            int c = cnt[idx];
            rowoff[idx] = running;
            running += c;
            dis[idx] = rsqrtf((float)(c + 1));
        }
    }
    if (t == 1023) rowoff[N_NODES] = part[1023];
}

__global__ void k_fill(const int* __restrict__ ei, const int* __restrict__ rowoff,
                       int* __restrict__ cur, int* __restrict__ csrc)
{
    int e = blockIdx.x * blockDim.x + threadIdx.x;
    if (e < N_EDGES) {
        int s = ei[e];
        int d = ei[N_EDGES + e];
        int pos = rowoff[d] + atomicAdd(&cur[d], 1);
        csrc[pos] = s;
    }
}

// ---------------- TF32 tensor-core GEMM -------------------------------------
// C[M,Ncols] = op(A[M,K]) @ B[K,Ncols] (+bias)(+relu)
// block tile 128x128, BK=32, 8 warps (4 in M x 2 in N), warp tile 32x64
__device__ __forceinline__ uint32_t f2tf32(float f) {
    uint32_t r;
    asm("cvt.rna.tf32.f32 %0, %1;" : "=r"(r) : "f"(f));
    return r;
}

template<bool RELU_A, bool BIAS, bool RELU_OUT>
__global__ void __launch_bounds__(256, 2) k_gemm_tc(
    const float* __restrict__ A, const float* __restrict__ B,
    const float* __restrict__ bias, float* __restrict__ C,
    int M, int Ncols, int K)
{
    __shared__ float As[128][36];   // pad: bank = 4*row + col (mod 32)
    __shared__ float Bs[32][132];   // pad: bank = 4*k + n (mod 32)

    const int tid    = threadIdx.x;
    const int lane   = tid & 31;
    const int wid    = tid >> 5;
    const int warp_m = wid & 3;     // 0..3 -> 32-row slice
    const int warp_n = wid >> 2;    // 0..1 -> 64-col slice
    const int row0   = blockIdx.x * 128;
    const int col0   = blockIdx.y * 128;

    const int g  = lane >> 2;       // group id 0..7
    const int tg = lane & 3;        // thread-in-group 0..3

    float c[2][8][4];
#pragma unroll
    for (int mf = 0; mf < 2; mf++)
#pragma unroll
        for (int nf = 0; nf < 8; nf++)
#pragma unroll
            for (int i = 0; i < 4; i++) c[mf][nf][i] = 0.0f;

    // global load mapping
    const int a_r  = tid >> 3;          // 0..31 (+32*i)
    const int a_c4 = (tid & 7) * 4;     // float4 col
    const int b_k  = tid >> 5;          // 0..7 (+8*j)
    const int b_c4 = (lane) * 4;        // float4 col within 128

    for (int k0 = 0; k0 < K; k0 += 32) {
        // load A tile 128x32
#pragma unroll
        for (int i = 0; i < 4; i++) {
            int r = a_r + i * 32;
            float4 v = make_float4(0.f, 0.f, 0.f, 0.f);
            if (row0 + r < M)
                v = *(const float4*)(A + (size_t)(row0 + r) * K + k0 + a_c4);
            if (RELU_A) {
                v.x = fmaxf(v.x, 0.f); v.y = fmaxf(v.y, 0.f);
                v.z = fmaxf(v.z, 0.f); v.w = fmaxf(v.w, 0.f);
            }
            *(float4*)&As[r][a_c4] = v;
        }
        // load B tile 32x128
#pragma unroll
        for (int j = 0; j < 4; j++) {
            int k = b_k + j * 8;
            float4 v = *(const float4*)(B + (size_t)(k0 + k) * Ncols + col0 + b_c4);
            *(float4*)&Bs[k][b_c4] = v;
        }
        __syncthreads();

#pragma unroll
        for (int kk = 0; kk < 4; kk++) {
            const int kb = kk * 8;
            // A fragments: 2 x m16
            uint32_t af[2][4];
#pragma unroll
            for (int mf = 0; mf < 2; mf++) {
                int rs = warp_m * 32 + mf * 16 + g;
                af[mf][0] = f2tf32(As[rs    ][kb + tg    ]);
                af[mf][1] = f2tf32(As[rs + 8][kb + tg    ]);
                af[mf][2] = f2tf32(As[rs    ][kb + tg + 4]);
                af[mf][3] = f2tf32(As[rs + 8][kb + tg + 4]);
            }
            // B fragments: 8 x n8
            uint32_t bf[8][2];
#pragma unroll
            for (int nf = 0; nf < 8; nf++) {
                int ns = warp_n * 64 + nf * 8 + g;
                bf[nf][0] = f2tf32(Bs[kb + tg    ][ns]);
                bf[nf][1] = f2tf32(Bs[kb + tg + 4][ns]);
            }
#pragma unroll
            for (int mf = 0; mf < 2; mf++)
#pragma unroll
                for (int nf = 0; nf < 8; nf++) {
                    asm volatile(
                        "mma.sync.aligned.m16n8k8.row.col.f32.tf32.tf32.f32 "
                        "{%0,%1,%2,%3}, {%4,%5,%6,%7}, {%8,%9}, {%0,%1,%2,%3};"
                        : "+f"(c[mf][nf][0]), "+f"(c[mf][nf][1]),
                          "+f"(c[mf][nf][2]), "+f"(c[mf][nf][3])
                        : "r"(af[mf][0]), "r"(af[mf][1]), "r"(af[mf][2]), "r"(af[mf][3]),
                          "r"(bf[nf][0]), "r"(bf[nf][1]));
                }
        }
        __syncthreads();
    }

    // epilogue
#pragma unroll
    for (int mf = 0; mf < 2; mf++) {
        int rbase = row0 + warp_m * 32 + mf * 16 + g;
#pragma unroll
        for (int nf = 0; nf < 8; nf++) {
            int col = col0 + warp_n * 64 + nf * 8 + tg * 2;
            float b0 = 0.f, b1 = 0.f;
            if (BIAS) { b0 = bias[col]; b1 = bias[col + 1]; }
#pragma unroll
            for (int half = 0; half < 2; half++) {
                int r = rbase + half * 8;
                if (r < M) {
                    float v0 = c[mf][nf][half * 2 + 0] + b0;
                    float v1 = c[mf][nf][half * 2 + 1] + b1;
                    if (RELU_OUT) { v0 = fmaxf(v0, 0.f); v1 = fmaxf(v1, 0.f); }
                    float2 o = make_float2(v0, v1);
                    *(float2*)(C + (size_t)r * Ncols + col) = o;
                }
            }
        }
    }
}

// ---------------- CSR gather aggregation (one warp per dst node) ------------
__global__ void __launch_bounds__(256) k_gather(
    const int* __restrict__ csrc, const int* __restrict__ rowoff,
    const float* __restrict__ dis, const float* __restrict__ t,
    const float* __restrict__ bias, float* __restrict__ h)
{
    int w    = (blockIdx.x * 256 + threadIdx.x) >> 5;
    int lane = threadIdx.x & 31;
    if (w >= N_NODES) return;

    int beg = rowoff[w], end = rowoff[w + 1];
    float dd = dis[w];

    float4 acc = make_float4(0.f, 0.f, 0.f, 0.f);
    for (int eb = beg; eb < end; eb += 32) {
        int n = end - eb; if (n > 32) n = 32;
        int   s_l  = (lane < n) ? __ldg(csrc + eb + lane) : 0;
        float ns_l = (lane < n) ? __ldg(dis + s_l) : 0.f;
#pragma unroll 4
        for (int j = 0; j < n; j++) {
            int   s  = __shfl_sync(0xffffffffu, s_l,  j);
            float ns = __shfl_sync(0xffffffffu, ns_l, j);
            float4 v = *(const float4*)(t + (size_t)s * D_HID + lane * 4);
            acc.x = fmaf(ns, v.x, acc.x); acc.y = fmaf(ns, v.y, acc.y);
            acc.z = fmaf(ns, v.z, acc.z); acc.w = fmaf(ns, v.w, acc.w);
        }
    }

    float4 tv = *(const float4*)(t + (size_t)w * D_HID + lane * 4);
    float4 bv = ((const float4*)bias)[lane];
    float dd2 = dd * dd;
    float4 o;
    o.x = fmaf(dd, acc.x, fmaf(dd2, tv.x, bv.x));
    o.y = fmaf(dd, acc.y, fmaf(dd2, tv.y, bv.y));
    o.z = fmaf(dd, acc.z, fmaf(dd2, tv.z, bv.z));
    o.w = fmaf(dd, acc.w, fmaf(dd2, tv.w, bv.w));
    *(float4*)(h + (size_t)w * D_HID + lane * 4) = o;
}

// ---------------- final: out[M,10] = H[M,256] @ W[256,10] + b ---------------
__global__ void __launch_bounds__(256) k_final(
    const float* __restrict__ H, const float* __restrict__ W,
    const float* __restrict__ b, float* __restrict__ out, int M)
{
    __shared__ float sW[D_MLP * D_OUT];
    __shared__ float sb[D_OUT];
    for (int k = threadIdx.x; k < D_MLP * D_OUT; k += 256) sW[k] = W[k];
    if (threadIdx.x < D_OUT) sb[threadIdx.x] = b[threadIdx.x];
    __syncthreads();

    int w    = (blockIdx.x * 256 + threadIdx.x) >> 5;
    int lane = threadIdx.x & 31;
    if (w >= M) return;

    const float* hrow = H + (size_t)w * D_MLP;
    float acc[D_OUT];
#pragma unroll
    for (int j = 0; j < D_OUT; j++) acc[j] = 0.0f;

#pragma unroll
    for (int kk = 0; kk < D_MLP / 32; kk++) {
        int k = kk * 32 + lane;
        float hv = hrow[k];
        const float* wr = &sW[k * D_OUT];
#pragma unroll
        for (int j = 0; j < D_OUT; j++) acc[j] = fmaf(hv, wr[j], acc[j]);
    }
#pragma unroll
    for (int j = 0; j < D_OUT; j++) {
#pragma unroll
        for (int off = 16; off; off >>= 1)
            acc[j] += __shfl_down_sync(0xffffffffu, acc[j], off);
    }
    if (lane == 0) {
#pragma unroll
        for (int j = 0; j < D_OUT; j++)
            out[(size_t)w * D_OUT + j] = acc[j] + sb[j];
    }
}

// ---------------------------------------------------------------------------
extern "C" void kernel_launch(void* const* d_in, const int* in_sizes, int n_in,
                              void* d_out, int out_size)
{
    const float* x   = (const float*)d_in[0];
    const int*   ei  = (const int*)d_in[1];     // int32 (JAX x64 disabled)
    const float* W0  = (const float*)d_in[2];
    const float* b0  = (const float*)d_in[3];
    const float* W1  = (const float*)d_in[4];
    const float* b1  = (const float*)d_in[5];
    const float* Wm1 = (const float*)d_in[6];
    const float* bm1 = (const float*)d_in[7];
    const float* Wm2 = (const float*)d_in[8];
    const float* bm2 = (const float*)d_in[9];
    float* out = (float*)d_out;

    float *dis, *t, *h, *h2;
    int *cnt, *cur, *rowoff, *csrc;
    cudaGetSymbolAddress((void**)&dis, g_dis);
    cudaGetSymbolAddress((void**)&t,   g_t);
    cudaGetSymbolAddress((void**)&h,   g_h);
    cudaGetSymbolAddress((void**)&h2,  g_h2);
    cudaGetSymbolAddress((void**)&cnt, g_cnt);
    cudaGetSymbolAddress((void**)&cur, g_cur);
    cudaGetSymbolAddress((void**)&rowoff, g_rowoff);
    cudaGetSymbolAddress((void**)&csrc, g_csrc);

    const int ngrid = (N_NODES + 255) / 256;
    const int egrid = (N_EDGES + 255) / 256;

    // ---- CSR build (by dst) + norms ----
    k_zero <<<ngrid, 256>>>(cnt, cur);
    k_count<<<egrid, 256>>>(ei, cnt);
    k_scan <<<1, 1024>>>(cnt, rowoff, dis);
    k_fill <<<egrid, 256>>>(ei, rowoff, cur, csrc);

    const dim3 gemm_grid1((N_NODES + 127) / 128, 1);
    const dim3 gemm_grid2((N_NODES + 127) / 128, 2);
    const int  gather_grid = (N_NODES * 32 + 255) / 256;

    // layer 0
    k_gemm_tc<false, false, false><<<gemm_grid1, 256>>>(x, W0, nullptr, t, N_NODES, D_HID, D_IN);
    k_gather<<<gather_grid, 256>>>(csrc, rowoff, dis, t, b0, h);

    // layer 1 (relu fused into GEMM A-load)
    k_gemm_tc<true, false, false><<<gemm_grid1, 256>>>(h, W1, nullptr, t, N_NODES, D_HID, D_HID);
    k_gather<<<gather_grid, 256>>>(csrc, rowoff, dis, t, b1, h);

    // MLP head
    k_gemm_tc<false, true, true><<<gemm_grid2, 256>>>(h, Wm1, bm1, h2, N_NODES, D_MLP, D_HID);
    k_final<<<(N_NODES * 32 + 255) / 256, 256>>>(h2, Wm2, bm2, out, N_NODES);
}